// round 2
// baseline (speedup 1.0000x reference)
#include <cuda_runtime.h>

#define BB 8
#define SS 2048
#define HH 768
#define NHH 12
#define HDD 64

// Scratch: Q,K,V in [B, NH, S, HD] layout (fp32). 3 x 50.3 MB.
__device__ float g_q[BB * NHH * SS * HDD];
__device__ float g_k[BB * NHH * SS * HDD];
__device__ float g_v[BB * NHH * SS * HDD];

// ---------------------------------------------------------------------------
// Kernel 1: QKV projection.  out[t, n] = sum_k X[t,k] * W[n,k] + b[n]
// written directly into [B, NH, S, HD] head layout.
// Tile: 64x64 output per block, BK=16, 256 threads, 4x4 per thread.
// gridDim.z in {0,1,2} selects (Wq,bq,g_q), (Wk,bk,g_k), (Wv,bv,g_v).
// ---------------------------------------------------------------------------
#define PBM 64
#define PBN 64
#define PBK 16

__global__ __launch_bounds__(256)
void qkv_proj_kernel(const float* __restrict__ X,
                     const float* __restrict__ Wq, const float* __restrict__ bq,
                     const float* __restrict__ Wk, const float* __restrict__ bk,
                     const float* __restrict__ Wv, const float* __restrict__ bv)
{
    const float* W;
    const float* bias;
    float* out;
    if (blockIdx.z == 0)      { W = Wq; bias = bq; out = g_q; }
    else if (blockIdx.z == 1) { W = Wk; bias = bk; out = g_k; }
    else                      { W = Wv; bias = bv; out = g_v; }

    __shared__ float As[PBK][PBM];   // As[kk][i] = X[t0+i][k0+kk]
    __shared__ float Bs[PBK][PBN];   // Bs[kk][j] = W[n0+j][k0+kk]

    const int t0  = blockIdx.x * PBM;
    const int n0  = blockIdx.y * PBN;
    const int tid = threadIdx.x;          // 0..255
    const int tx  = tid & 15;
    const int ty  = tid >> 4;

    float acc[4][4] = {};

    const int li   = tid >> 2;           // 0..63 (row within tile for loading)
    const int lk4  = (tid & 3) * 4;      // 0,4,8,12

    for (int k0 = 0; k0 < HH; k0 += PBK) {
        // load X tile (64 rows x 16 cols) and W tile, transposed into smem
        float4 xv = *reinterpret_cast<const float4*>(&X[(t0 + li) * HH + k0 + lk4]);
        As[lk4 + 0][li] = xv.x; As[lk4 + 1][li] = xv.y;
        As[lk4 + 2][li] = xv.z; As[lk4 + 3][li] = xv.w;
        float4 wv = *reinterpret_cast<const float4*>(&W[(n0 + li) * HH + k0 + lk4]);
        Bs[lk4 + 0][li] = wv.x; Bs[lk4 + 1][li] = wv.y;
        Bs[lk4 + 2][li] = wv.z; Bs[lk4 + 3][li] = wv.w;
        __syncthreads();

        #pragma unroll
        for (int kk = 0; kk < PBK; kk++) {
            float4 a = *reinterpret_cast<const float4*>(&As[kk][ty * 4]);
            float4 b = *reinterpret_cast<const float4*>(&Bs[kk][tx * 4]);
            float av[4] = {a.x, a.y, a.z, a.w};
            float bv4[4] = {b.x, b.y, b.z, b.w};
            #pragma unroll
            for (int i = 0; i < 4; i++)
                #pragma unroll
                for (int j = 0; j < 4; j++)
                    acc[i][j] += av[i] * bv4[j];
        }
        __syncthreads();
    }

    // epilogue: add bias, scatter to [B, NH, S, HD]
    #pragma unroll
    for (int i = 0; i < 4; i++) {
        const int t  = t0 + ty * 4 + i;
        const int b_ = t / SS;
        const int s  = t % SS;
        #pragma unroll
        for (int j = 0; j < 4; j++) {
            const int n = n0 + tx * 4 + j;
            const int h = n >> 6;        // n / HD
            const int d = n & 63;        // n % HD
            out[(((b_ * NHH + h) * SS) + s) * HDD + d] = acc[i][j] + bias[n];
        }
    }
}

// ---------------------------------------------------------------------------
// Kernel 2: flash attention, fp32.
// Block = (q-tile of 64 rows, head, batch). 256 threads.
// Per iteration over 32 key tiles of 64: S = Q K^T * 1/8 + mask, online
// softmax, O += P V with rescale. Dynamic smem (Qs + Ks + Ps + Vs ~ 67 KB).
// ---------------------------------------------------------------------------
#define QS_STRIDE 65
#define KS_STRIDE 65
#define PS_STRIDE 65
#define VS_STRIDE 64

#define SM_QS   0
#define SM_KS   (SM_QS + 64 * QS_STRIDE)
#define SM_PS   (SM_KS + 64 * KS_STRIDE)
#define SM_VS   (SM_PS + 64 * PS_STRIDE)
#define SM_M    (SM_VS + 64 * VS_STRIDE)
#define SM_L    (SM_M + 64)
#define SM_SC   (SM_L + 64)
#define SM_FLOATS (SM_SC + 64)
#define ATTN_SMEM_BYTES (SM_FLOATS * 4)

__global__ __launch_bounds__(256)
void flash_attn_kernel(const float* __restrict__ mask, float* __restrict__ out)
{
    extern __shared__ float sm[];
    float* Qs = sm + SM_QS;   // [64][65]
    float* Ks = sm + SM_KS;   // [64][65]
    float* Ps = sm + SM_PS;   // [64][65]
    float* Vs = sm + SM_VS;   // [64][64]
    float* m_s = sm + SM_M;
    float* l_s = sm + SM_L;
    float* sc_s = sm + SM_SC;

    const int qt = blockIdx.x;   // 0..31
    const int h  = blockIdx.y;   // 0..11
    const int b  = blockIdx.z;   // 0..7
    const int tid = threadIdx.x;
    const int tx  = tid & 15;
    const int ty  = tid >> 4;

    const float* qptr  = g_q + ((size_t)(b * NHH + h) * SS + qt * 64) * HDD;
    const float* kbase = g_k + (size_t)(b * NHH + h) * SS * HDD;
    const float* vbase = g_v + (size_t)(b * NHH + h) * SS * HDD;
    const float* mrow  = mask + b * SS;

    // load Q tile: 64x64 floats via float4 (256 threads x 4 float4)
    #pragma unroll
    for (int e = 0; e < 4; e++) {
        int idx = tid + e * 256;       // float4 index 0..1023
        int r   = idx >> 4;            // 16 float4 per row
        int c4  = (idx & 15) * 4;
        float4 v = *reinterpret_cast<const float4*>(&qptr[r * 64 + c4]);
        Qs[r * QS_STRIDE + c4 + 0] = v.x;
        Qs[r * QS_STRIDE + c4 + 1] = v.y;
        Qs[r * QS_STRIDE + c4 + 2] = v.z;
        Qs[r * QS_STRIDE + c4 + 3] = v.w;
    }
    if (tid < 64) { m_s[tid] = -1e30f; l_s[tid] = 0.0f; }

    float acc[4][4] = {};
    const float inv_sqrt = 0.125f;   // 1/sqrt(64)

    for (int kt = 0; kt < SS / 64; kt++) {
        __syncthreads();   // previous PV done before overwriting Ks/Vs

        // load K,V tiles
        #pragma unroll
        for (int e = 0; e < 4; e++) {
            int idx = tid + e * 256;
            int r   = idx >> 4;
            int c4  = (idx & 15) * 4;
            float4 kv = *reinterpret_cast<const float4*>(&kbase[(kt * 64 + r) * 64 + c4]);
            Ks[r * KS_STRIDE + c4 + 0] = kv.x;
            Ks[r * KS_STRIDE + c4 + 1] = kv.y;
            Ks[r * KS_STRIDE + c4 + 2] = kv.z;
            Ks[r * KS_STRIDE + c4 + 3] = kv.w;
            float4 vv = *reinterpret_cast<const float4*>(&vbase[(kt * 64 + r) * 64 + c4]);
            *reinterpret_cast<float4*>(&Vs[r * VS_STRIDE + c4]) = vv;
        }
        __syncthreads();

        // scores: this thread computes S[ty*4+i][tx*4+j]
        float sc[4][4] = {};
        #pragma unroll 16
        for (int d = 0; d < 64; d++) {
            float av[4], bv4[4];
            #pragma unroll
            for (int u = 0; u < 4; u++) av[u]  = Qs[(ty * 4 + u) * QS_STRIDE + d];
            #pragma unroll
            for (int u = 0; u < 4; u++) bv4[u] = Ks[(tx * 4 + u) * KS_STRIDE + d];
            #pragma unroll
            for (int i = 0; i < 4; i++)
                #pragma unroll
                for (int j = 0; j < 4; j++)
                    sc[i][j] += av[i] * bv4[j];
        }
        // write scaled + masked scores
        #pragma unroll
        for (int j = 0; j < 4; j++) {
            float mj = mrow[kt * 64 + tx * 4 + j];
            #pragma unroll
            for (int i = 0; i < 4; i++)
                Ps[(ty * 4 + i) * PS_STRIDE + tx * 4 + j] = sc[i][j] * inv_sqrt + mj;
        }
        __syncthreads();

        // per-row online softmax stats (rows 0..63 by threads 0..63)
        if (tid < 64) {
            float mo = m_s[tid];
            float mx = mo;
            float* row = Ps + tid * PS_STRIDE;
            #pragma unroll 8
            for (int j = 0; j < 64; j++) mx = fmaxf(mx, row[j]);
            float rescale = __expf(mo - mx);
            float sum = 0.0f;
            #pragma unroll 8
            for (int j = 0; j < 64; j++) {
                float p = __expf(row[j] - mx);
                row[j] = p;
                sum += p;
            }
            m_s[tid]  = mx;
            l_s[tid]  = l_s[tid] * rescale + sum;
            sc_s[tid] = rescale;
        }
        __syncthreads();

        // rescale accumulators, then O += P @ V
        float rs[4];
        #pragma unroll
        for (int i = 0; i < 4; i++) rs[i] = sc_s[ty * 4 + i];
        #pragma unroll
        for (int i = 0; i < 4; i++)
            #pragma unroll
            for (int j = 0; j < 4; j++)
                acc[i][j] *= rs[i];

        #pragma unroll 8
        for (int j = 0; j < 64; j++) {
            float p[4];
            #pragma unroll
            for (int i = 0; i < 4; i++) p[i] = Ps[(ty * 4 + i) * PS_STRIDE + j];
            float4 vv = *reinterpret_cast<const float4*>(&Vs[j * VS_STRIDE + tx * 4]);
            #pragma unroll
            for (int i = 0; i < 4; i++) {
                acc[i][0] += p[i] * vv.x;
                acc[i][1] += p[i] * vv.y;
                acc[i][2] += p[i] * vv.z;
                acc[i][3] += p[i] * vv.w;
            }
        }
    }
    __syncthreads();

    // epilogue: divide by l, write ctx[b, s, h*64 + d]
    #pragma unroll
    for (int i = 0; i < 4; i++) {
        const int s = qt * 64 + ty * 4 + i;
        const float inv_l = 1.0f / l_s[ty * 4 + i];
        float4 o;
        o.x = acc[i][0] * inv_l;
        o.y = acc[i][1] * inv_l;
        o.z = acc[i][2] * inv_l;
        o.w = acc[i][3] * inv_l;
        *reinterpret_cast<float4*>(
            &out[((size_t)(b * SS + s) * HH) + h * 64 + tx * 4]) = o;
    }
}

// ---------------------------------------------------------------------------
// Launch
// ---------------------------------------------------------------------------
extern "C" void kernel_launch(void* const* d_in, const int* in_sizes, int n_in,
                              void* d_out, int out_size)
{
    const float* X    = (const float*)d_in[0];
    const float* mask = (const float*)d_in[1];
    const float* Wq   = (const float*)d_in[2];
    const float* bq   = (const float*)d_in[3];
    const float* Wk   = (const float*)d_in[4];
    const float* bk   = (const float*)d_in[5];
    const float* Wv   = (const float*)d_in[6];
    const float* bv   = (const float*)d_in[7];
    float* out = (float*)d_out;

    // QKV projections: grid (M/64, N/64, 3)
    dim3 gproj((BB * SS) / PBM, HH / PBN, 3);
    qkv_proj_kernel<<<gproj, 256>>>(X, Wq, bq, Wk, bk, Wv, bv);

    // Flash attention
    cudaFuncSetAttribute(flash_attn_kernel,
                         cudaFuncAttributeMaxDynamicSharedMemorySize,
                         ATTN_SMEM_BYTES);
    dim3 gattn(SS / 64, NHH, BB);
    flash_attn_kernel<<<gattn, 256, ATTN_SMEM_BYTES>>>(mask, out);
}

// round 4
// speedup vs baseline: 3.6176x; 3.6176x over previous
#include <cuda_runtime.h>

#define BB 8
#define SS 2048
#define HH 768
#define NHH 12
#define HDD 64

// Scratch: Q,K,V in [B, NH, S, HD] layout (fp32).
__device__ float g_q[BB * NHH * SS * HDD];
__device__ float g_k[BB * NHH * SS * HDD];
__device__ float g_v[BB * NHH * SS * HDD];

// ---------------------------------------------------------------------------
// helpers: tf32 rounding + m16n8k8 tf32 mma
// ---------------------------------------------------------------------------
__device__ __forceinline__ unsigned f2tf(float x) {
    unsigned u;
    asm("cvt.rna.tf32.f32 %0, %1;" : "=r"(u) : "f"(x));
    return u;
}
__device__ __forceinline__ float f2tf_f(float x) {
    return __uint_as_float(f2tf(x));
}

__device__ __forceinline__ void mma8(float& c0, float& c1, float& c2, float& c3,
                                     unsigned a0, unsigned a1, unsigned a2, unsigned a3,
                                     unsigned b0, unsigned b1) {
    asm volatile(
        "mma.sync.aligned.m16n8k8.row.col.f32.tf32.tf32.f32 "
        "{%0,%1,%2,%3}, {%4,%5,%6,%7}, {%8,%9}, {%0,%1,%2,%3};"
        : "+f"(c0), "+f"(c1), "+f"(c2), "+f"(c3)
        : "r"(a0), "r"(a1), "r"(a2), "r"(a3), "r"(b0), "r"(b1));
}

// ---------------------------------------------------------------------------
// Kernel 1: QKV projection via tf32 tensor cores.
// C[t, n] = sum_k X[t,k] * W[n,k] + b[n], scattered into [B, NH, S, HD].
// Block tile 128x128, K-chunk 32, 8 warps (4m x 2n) of 32x64 warp tiles.
// smem padded to stride 36 floats -> conflict-free fragment reads.
// ---------------------------------------------------------------------------
#define XS_STR 36
#define WS_STR 36

__global__ __launch_bounds__(256)
void qkv_proj_tc(const float* __restrict__ X,
                 const float* __restrict__ Wq, const float* __restrict__ bq,
                 const float* __restrict__ Wk, const float* __restrict__ bk,
                 const float* __restrict__ Wv, const float* __restrict__ bv)
{
    const float* W;
    const float* bias;
    float* out;
    if (blockIdx.z == 0)      { W = Wq; bias = bq; out = g_q; }
    else if (blockIdx.z == 1) { W = Wk; bias = bk; out = g_k; }
    else                      { W = Wv; bias = bv; out = g_v; }

    __shared__ float Xs[128 * XS_STR];
    __shared__ float Ws[128 * WS_STR];

    const int tid  = threadIdx.x;
    const int wid  = tid >> 5;
    const int lane = tid & 31;
    const int g    = lane >> 2;   // group id 0..7
    const int tig  = lane & 3;    // thread in group 0..3
    const int wm   = wid >> 1;    // 0..3
    const int wn   = wid & 1;     // 0..1

    const int t0 = blockIdx.x * 128;
    const int n0 = blockIdx.y * 128;

    float acc[2][8][4] = {};

    for (int k0 = 0; k0 < HH; k0 += 32) {
        __syncthreads();
        // load X tile [128 x 32] and W tile [128 x 32], tf32-rounded.
        // 128 rows x 8 float4/row = 1024 float4 slots -> e < 4 with 256 threads.
        #pragma unroll
        for (int e = 0; e < 4; e++) {
            int idx = tid + e * 256;       // 0..1023 float4 slots
            int r   = idx >> 3;            // 8 float4 per row -> rows 0..127
            int c4  = (idx & 7) << 2;
            float4 xv = *reinterpret_cast<const float4*>(&X[(size_t)(t0 + r) * HH + k0 + c4]);
            Xs[r * XS_STR + c4 + 0] = f2tf_f(xv.x);
            Xs[r * XS_STR + c4 + 1] = f2tf_f(xv.y);
            Xs[r * XS_STR + c4 + 2] = f2tf_f(xv.z);
            Xs[r * XS_STR + c4 + 3] = f2tf_f(xv.w);
            float4 wv = *reinterpret_cast<const float4*>(&W[(size_t)(n0 + r) * HH + k0 + c4]);
            Ws[r * WS_STR + c4 + 0] = f2tf_f(wv.x);
            Ws[r * WS_STR + c4 + 1] = f2tf_f(wv.y);
            Ws[r * WS_STR + c4 + 2] = f2tf_f(wv.z);
            Ws[r * WS_STR + c4 + 3] = f2tf_f(wv.w);
        }
        __syncthreads();

        #pragma unroll
        for (int ks = 0; ks < 4; ks++) {      // k-steps of 8
            unsigned a[2][4];
            #pragma unroll
            for (int mt = 0; mt < 2; mt++) {
                int row = wm * 32 + mt * 16;
                a[mt][0] = __float_as_uint(Xs[(row + g    ) * XS_STR + ks * 8 + tig    ]);
                a[mt][1] = __float_as_uint(Xs[(row + g + 8) * XS_STR + ks * 8 + tig    ]);
                a[mt][2] = __float_as_uint(Xs[(row + g    ) * XS_STR + ks * 8 + tig + 4]);
                a[mt][3] = __float_as_uint(Xs[(row + g + 8) * XS_STR + ks * 8 + tig + 4]);
            }
            #pragma unroll
            for (int nt = 0; nt < 8; nt++) {
                int col = wn * 64 + nt * 8;
                unsigned b0 = __float_as_uint(Ws[(col + g) * WS_STR + ks * 8 + tig    ]);
                unsigned b1 = __float_as_uint(Ws[(col + g) * WS_STR + ks * 8 + tig + 4]);
                mma8(acc[0][nt][0], acc[0][nt][1], acc[0][nt][2], acc[0][nt][3],
                     a[0][0], a[0][1], a[0][2], a[0][3], b0, b1);
                mma8(acc[1][nt][0], acc[1][nt][1], acc[1][nt][2], acc[1][nt][3],
                     a[1][0], a[1][1], a[1][2], a[1][3], b0, b1);
            }
        }
    }

    // epilogue: add bias, scatter to [B, NH, S, HD]
    #pragma unroll
    for (int mt = 0; mt < 2; mt++) {
        #pragma unroll
        for (int ci = 0; ci < 2; ci++) {      // row half: +0 / +8
            const int row = wm * 32 + mt * 16 + g + ci * 8;
            const int t   = t0 + row;
            const int b_  = t / SS;
            const int s   = t % SS;
            #pragma unroll
            for (int nt = 0; nt < 8; nt++) {
                const int col = wn * 64 + nt * 8 + 2 * tig;
                const int n   = n0 + col;
                const int h   = n >> 6;
                const int d   = n & 63;
                float* dst = &out[(((size_t)(b_ * NHH + h) * SS) + s) * HDD + d];
                dst[0] = acc[mt][nt][ci * 2 + 0] + bias[n];
                dst[1] = acc[mt][nt][ci * 2 + 1] + bias[n + 1];
            }
        }
    }
}

// ---------------------------------------------------------------------------
// Kernel 2: flash attention, tf32 tensor cores (FA2-style).
// 256 threads / 8 warps, Q tile 128 rows (16 per warp), K tile 64.
// Q held in register A-fragments (pre-scaled by 1/8). S acc in registers,
// row softmax via quad shuffles, P through smem to re-layout for PV mma.
// ---------------------------------------------------------------------------
#define KS_STR 68   // bank-conflict-free for [row][col-frag] reads (4r+c)
#define VS_STR 72   // conflict-free for [k][n-frag] reads (8r+c)
#define PS_STR 68

#define SM_KS 0
#define SM_VS (SM_KS + 64 * KS_STR)                 // 4352
#define SM_PS (SM_VS + 64 * VS_STR)                 // 4352+4608 = 8960
#define SM_MS (SM_PS + 128 * PS_STR)                // + 8704 = 17664
#define ATTN_SMEM_FLOATS (SM_MS + SS)               // + 2048 = 19712
#define ATTN_SMEM_BYTES (ATTN_SMEM_FLOATS * 4)      // 78848

__global__ __launch_bounds__(256)
void flash_attn_tc(const float* __restrict__ mask, float* __restrict__ out)
{
    extern __shared__ float sm[];
    float* Ks = sm + SM_KS;
    float* Vs = sm + SM_VS;
    float* Ps = sm + SM_PS;
    float* Ms = sm + SM_MS;

    const int qt   = blockIdx.x;   // 0..15 (tiles of 128 q rows)
    const int h    = blockIdx.y;
    const int b    = blockIdx.z;
    const int tid  = threadIdx.x;
    const int wid  = tid >> 5;     // 0..7
    const int lane = tid & 31;
    const int g    = lane >> 2;
    const int tig  = lane & 3;

    const float* kbase = g_k + (size_t)(b * NHH + h) * SS * HDD;
    const float* vbase = g_v + (size_t)(b * NHH + h) * SS * HDD;

    // mask row for this batch into smem
    for (int i = tid; i < SS; i += 256) Ms[i] = mask[b * SS + i];

    // Q fragments: 16 rows per warp, pre-scaled by 1/8, tf32-rounded.
    const float* qptr = g_q + ((size_t)(b * NHH + h) * SS + qt * 128 + wid * 16) * HDD;
    unsigned qf[8][4];
    #pragma unroll
    for (int kk = 0; kk < 8; kk++) {
        qf[kk][0] = f2tf(0.125f * qptr[(g    ) * HDD + kk * 8 + tig    ]);
        qf[kk][1] = f2tf(0.125f * qptr[(g + 8) * HDD + kk * 8 + tig    ]);
        qf[kk][2] = f2tf(0.125f * qptr[(g    ) * HDD + kk * 8 + tig + 4]);
        qf[kk][3] = f2tf(0.125f * qptr[(g + 8) * HDD + kk * 8 + tig + 4]);
    }

    float m1 = -1e30f, m2 = -1e30f, l1 = 0.0f, l2 = 0.0f;
    float oacc[8][4] = {};

    const int prow1 = wid * 16 + g;      // this lane's two P rows (block-rel)
    const int prow2 = prow1 + 8;

    for (int kt = 0; kt < SS / 64; kt++) {
        __syncthreads();   // previous PV reads of Vs done

        // load K,V tiles (64x64), tf32-rounded
        #pragma unroll
        for (int e = 0; e < 4; e++) {
            int idx = tid + e * 256;   // 1024 float4 slots
            int r   = idx >> 4;
            int c4  = (idx & 15) << 2;
            float4 kv = *reinterpret_cast<const float4*>(&kbase[(size_t)(kt * 64 + r) * HDD + c4]);
            Ks[r * KS_STR + c4 + 0] = f2tf_f(kv.x);
            Ks[r * KS_STR + c4 + 1] = f2tf_f(kv.y);
            Ks[r * KS_STR + c4 + 2] = f2tf_f(kv.z);
            Ks[r * KS_STR + c4 + 3] = f2tf_f(kv.w);
            float4 vv = *reinterpret_cast<const float4*>(&vbase[(size_t)(kt * 64 + r) * HDD + c4]);
            Vs[r * VS_STR + c4 + 0] = f2tf_f(vv.x);
            Vs[r * VS_STR + c4 + 1] = f2tf_f(vv.y);
            Vs[r * VS_STR + c4 + 2] = f2tf_f(vv.z);
            Vs[r * VS_STR + c4 + 3] = f2tf_f(vv.w);
        }
        __syncthreads();

        // S = (Q/8) @ K^T  (16 x 64 per warp)
        float sacc[8][4] = {};
        #pragma unroll
        for (int kk = 0; kk < 8; kk++) {
            #pragma unroll
            for (int nt = 0; nt < 8; nt++) {
                unsigned b0 = __float_as_uint(Ks[(nt * 8 + g) * KS_STR + kk * 8 + tig    ]);
                unsigned b1 = __float_as_uint(Ks[(nt * 8 + g) * KS_STR + kk * 8 + tig + 4]);
                mma8(sacc[nt][0], sacc[nt][1], sacc[nt][2], sacc[nt][3],
                     qf[kk][0], qf[kk][1], qf[kk][2], qf[kk][3], b0, b1);
            }
        }

        // mask + row max
        float mx1 = -1e30f, mx2 = -1e30f;
        #pragma unroll
        for (int nt = 0; nt < 8; nt++) {
            float mk0 = Ms[kt * 64 + nt * 8 + 2 * tig];
            float mk1 = Ms[kt * 64 + nt * 8 + 2 * tig + 1];
            sacc[nt][0] += mk0; sacc[nt][1] += mk1;
            sacc[nt][2] += mk0; sacc[nt][3] += mk1;
            mx1 = fmaxf(mx1, fmaxf(sacc[nt][0], sacc[nt][1]));
            mx2 = fmaxf(mx2, fmaxf(sacc[nt][2], sacc[nt][3]));
        }
        mx1 = fmaxf(mx1, __shfl_xor_sync(0xffffffffu, mx1, 1));
        mx1 = fmaxf(mx1, __shfl_xor_sync(0xffffffffu, mx1, 2));
        mx2 = fmaxf(mx2, __shfl_xor_sync(0xffffffffu, mx2, 1));
        mx2 = fmaxf(mx2, __shfl_xor_sync(0xffffffffu, mx2, 2));

        float mn1 = fmaxf(m1, mx1);
        float mn2 = fmaxf(m2, mx2);
        float rs1 = __expf(m1 - mn1);
        float rs2 = __expf(m2 - mn2);
        m1 = mn1; m2 = mn2;

        float sum1 = 0.0f, sum2 = 0.0f;
        #pragma unroll
        for (int nt = 0; nt < 8; nt++) {
            float p0 = __expf(sacc[nt][0] - m1);
            float p1 = __expf(sacc[nt][1] - m1);
            float p2 = __expf(sacc[nt][2] - m2);
            float p3 = __expf(sacc[nt][3] - m2);
            sum1 += p0 + p1;
            sum2 += p2 + p3;
            float2 w1 = make_float2(f2tf_f(p0), f2tf_f(p1));
            float2 w2 = make_float2(f2tf_f(p2), f2tf_f(p3));
            *reinterpret_cast<float2*>(&Ps[prow1 * PS_STR + nt * 8 + 2 * tig]) = w1;
            *reinterpret_cast<float2*>(&Ps[prow2 * PS_STR + nt * 8 + 2 * tig]) = w2;
        }
        sum1 += __shfl_xor_sync(0xffffffffu, sum1, 1);
        sum1 += __shfl_xor_sync(0xffffffffu, sum1, 2);
        sum2 += __shfl_xor_sync(0xffffffffu, sum2, 1);
        sum2 += __shfl_xor_sync(0xffffffffu, sum2, 2);
        l1 = l1 * rs1 + sum1;
        l2 = l2 * rs2 + sum2;

        #pragma unroll
        for (int j = 0; j < 8; j++) {
            oacc[j][0] *= rs1; oacc[j][1] *= rs1;
            oacc[j][2] *= rs2; oacc[j][3] *= rs2;
        }
        __syncwarp();

        // O += P @ V   (16 x 64 per warp, K = 64 keys)
        #pragma unroll
        for (int kk = 0; kk < 8; kk++) {
            unsigned pa0 = __float_as_uint(Ps[prow1 * PS_STR + kk * 8 + tig    ]);
            unsigned pa1 = __float_as_uint(Ps[prow2 * PS_STR + kk * 8 + tig    ]);
            unsigned pa2 = __float_as_uint(Ps[prow1 * PS_STR + kk * 8 + tig + 4]);
            unsigned pa3 = __float_as_uint(Ps[prow2 * PS_STR + kk * 8 + tig + 4]);
            #pragma unroll
            for (int j2 = 0; j2 < 8; j2++) {
                unsigned b0 = __float_as_uint(Vs[(kk * 8 + tig    ) * VS_STR + j2 * 8 + g]);
                unsigned b1 = __float_as_uint(Vs[(kk * 8 + tig + 4) * VS_STR + j2 * 8 + g]);
                mma8(oacc[j2][0], oacc[j2][1], oacc[j2][2], oacc[j2][3],
                     pa0, pa1, pa2, pa3, b0, b1);
            }
        }
        __syncwarp();   // PV reads done before next iter overwrites Ps
    }

    // epilogue: O / l, write ctx[b, s, h*64 + d]
    const float inv1 = 1.0f / l1;
    const float inv2 = 1.0f / l2;
    const int s1 = qt * 128 + wid * 16 + g;
    const int s2 = s1 + 8;
    #pragma unroll
    for (int j2 = 0; j2 < 8; j2++) {
        const int d = j2 * 8 + 2 * tig;
        float2 o1 = make_float2(oacc[j2][0] * inv1, oacc[j2][1] * inv1);
        float2 o2 = make_float2(oacc[j2][2] * inv2, oacc[j2][3] * inv2);
        *reinterpret_cast<float2*>(&out[((size_t)(b * SS + s1) * HH) + h * 64 + d]) = o1;
        *reinterpret_cast<float2*>(&out[((size_t)(b * SS + s2) * HH) + h * 64 + d]) = o2;
    }
}

// ---------------------------------------------------------------------------
// Launch
// ---------------------------------------------------------------------------
extern "C" void kernel_launch(void* const* d_in, const int* in_sizes, int n_in,
                              void* d_out, int out_size)
{
    const float* X    = (const float*)d_in[0];
    const float* mask = (const float*)d_in[1];
    const float* Wq   = (const float*)d_in[2];
    const float* bq   = (const float*)d_in[3];
    const float* Wk   = (const float*)d_in[4];
    const float* bk   = (const float*)d_in[5];
    const float* Wv   = (const float*)d_in[6];
    const float* bv   = (const float*)d_in[7];
    float* out = (float*)d_out;

    dim3 gproj((BB * SS) / 128, HH / 128, 3);
    qkv_proj_tc<<<gproj, 256>>>(X, Wq, bq, Wk, bk, Wv, bv);

    cudaFuncSetAttribute(flash_attn_tc,
                         cudaFuncAttributeMaxDynamicSharedMemorySize,
                         ATTN_SMEM_BYTES);
    dim3 gattn(SS / 128, NHH, BB);
    flash_attn_tc<<<gattn, 256, ATTN_SMEM_BYTES>>>(mask, out);
}